// round 16
// baseline (speedup 1.0000x reference)
#include <cuda_runtime.h>
#include <cuda_bf16.h>
#include <cuda_fp16.h>
#include <cstdint>

#define NN 50000        // capacity: nodes
#define EE 800000       // capacity: edges
#define HID 128
#define MAXDEG 96       // bucket capacity; P(deg>96) < 1e-30 for this graph

// ---------------- scratch (static __device__, no allocation) ----------------
__device__ float g_h[NN * 128];
__device__ float g_h2[NN * 128];
__device__ float g_agg[NN * 128];
__device__ __half g_hx[NN * 128];    // fp16 copy of h   (aggregation input L1)
__device__ __half g_h2x[NN * 128];   // fp16 copy of h2  (aggregation input L2)
__device__ int   g_cnt[NN];          // per-node edge count
__device__ int   g_csr2[NN * MAXDEG];
__device__ __nv_bfloat16 g_Bhi1[128 * 256];   // B[o][k] = {W1_l | W1_r} hi
__device__ __nv_bfloat16 g_Blo1[128 * 256];   // residual lo
__device__ __nv_bfloat16 g_Bhi2[128 * 256];
__device__ __nv_bfloat16 g_Blo2[128 * 256];
__device__ int   g_E;        // true edge count (device-detected)
__device__ int   g_e64;      // edge_index is int64
__device__ int   g_x64;      // x is int64

// ---------------- warp-level bf16 MMA + ldmatrix (plain PTX) ----------------
__device__ __forceinline__ void mma16816(float* d, const uint32_t* a, const uint32_t* b) {
    asm volatile(
        "mma.sync.aligned.m16n8k16.row.col.f32.bf16.bf16.f32 "
        "{%0,%1,%2,%3}, {%4,%5,%6,%7}, {%8,%9}, {%0,%1,%2,%3};"
        : "+f"(d[0]), "+f"(d[1]), "+f"(d[2]), "+f"(d[3])
        : "r"(a[0]), "r"(a[1]), "r"(a[2]), "r"(a[3]), "r"(b[0]), "r"(b[1]));
}
__device__ __forceinline__ void ldsm4(uint32_t* r, uint32_t addr) {
    asm volatile("ldmatrix.sync.aligned.m8n8.x4.shared.b16 {%0,%1,%2,%3}, [%4];"
        : "=r"(r[0]), "=r"(r[1]), "=r"(r[2]), "=r"(r[3]) : "r"(addr));
}
__device__ __forceinline__ uint32_t smem_u32(const void* p) {
    uint32_t a;
    asm("{ .reg .u64 t; cvta.to.shared.u64 t, %1; cvt.u32.u64 %0, t; }" : "=r"(a) : "l"(p));
    return a;
}

// ---------------- init: zero cnt, thread0 does dtype/count detect ----------
__global__ void init_kernel(const int* __restrict__ ei, long long eiW,
                            const int* __restrict__ x, long long xW,
                            int elemMode, int n) {
    int i = blockIdx.x * blockDim.x + threadIdx.x;
    if (i < n) g_cnt[i] = 0;
    if (blockIdx.x == 0 && threadIdx.x == 0) {
        int e64 = 1;
        for (long long j = 1; j < 256 && j < eiW; j += 2)
            if (ei[j] != 0) { e64 = 0; break; }
        int x64 = 1;
        for (long long j = 1; j < 256 && j < xW; j += 2)
            if (x[j] != 0) { x64 = 0; break; }
        long long E;
        if (elemMode) E = eiW / 2;
        else          E = e64 ? eiW / 4 : eiW / 2;
        if (E > EE) E = EE;
        if (E < 0)  E = 0;
        g_E = (int)E;
        g_e64 = e64;
        g_x64 = x64;
    }
}

// ---------------- fused build: single-pass bucket CSR + gather + weight prep
__global__ void build_kernel(const int* __restrict__ ei,
                             const int* __restrict__ x, const float* __restrict__ emb,
                             int n, long long embRows,
                             const float* __restrict__ W1l, const float* __restrict__ W1r,
                             const float* __restrict__ W2l, const float* __restrict__ W2r,
                             int edgeBlocks) {
    if (blockIdx.x < edgeBlocks) {
        int i = blockIdx.x * blockDim.x + threadIdx.x;
        int E = g_E;
        if (i >= E) return;
        int e64 = g_e64;
        long long dstBase = e64 ? 2LL * E : (long long)E;
        int sv = e64 ? ei[2LL * i] : ei[i];
        int dv = e64 ? ei[dstBase + 2LL * i] : ei[dstBase + i];
        sv = max(0, min(sv, n - 1));
        dv = max(0, min(dv, n - 1));
        int pos = atomicAdd(&g_cnt[dv], 1);
        if (pos < MAXDEG) g_csr2[dv * MAXDEG + pos] = sv;
    } else {
        int idx = (blockIdx.x - edgeBlocks) * blockDim.x + threadIdx.x;
        int gWork = n * 32;
        if (idx < gWork) {
            int node = idx >> 5;
            int c4 = (idx & 31) * 4;
            long long row = g_x64 ? (long long)x[2LL * node] : (long long)x[node];
            if (row < 0) row = 0;
            if (row >= embRows) row = embRows - 1;
            float4 v = *(const float4*)(emb + row * 128 + c4);
            *(float4*)(g_h + (long long)node * 128 + c4) = v;
            __half2 p0 = __floats2half2_rn(v.x, v.y);
            __half2 p1 = __floats2half2_rn(v.z, v.w);
            __half2* hp = (__half2*)(g_hx + (long long)node * 128 + c4);
            hp[0] = p0;
            hp[1] = p1;
        } else {
            int w = idx - gWork;
            if (w >= 2 * 128 * 256) return;
            int which = w >> 15;
            int rem = w & 32767;
            int o = rem >> 8;
            int k = rem & 255;
            const float* Wl = which ? W2l : W1l;
            const float* Wr = which ? W2r : W1r;
            float v = (k < 128) ? Wl[o * 128 + k] : Wr[o * 128 + (k - 128)];
            __nv_bfloat16 hi = __float2bfloat16(v);
            __nv_bfloat16 lo = __float2bfloat16(v - __bfloat162float(hi));
            (which ? g_Bhi2 : g_Bhi1)[o * 256 + k] = hi;
            (which ? g_Blo2 : g_Blo1)[o * 256 + k] = lo;
        }
    }
}

// ---------------- mean aggregation: 2 nodes per warp, 16 lanes each ----------
__global__ void aggregate_kernel(const __half* __restrict__ hx,
                                 const int* __restrict__ ei, int n) {
    int warp = (blockIdx.x * blockDim.x + threadIdx.x) >> 5;
    int lane = threadIdx.x & 31;
    int node = warp * 2 + (lane >> 4);
    int sub = lane & 15;
    if (node >= n) return;
    int deg = g_cnt[node];
    float a0 = 0.f, a1 = 0.f, a2 = 0.f, a3 = 0.f;
    float a4 = 0.f, a5 = 0.f, a6 = 0.f, a7 = 0.f;
    if (deg <= MAXDEG) {
        const int* bucket = g_csr2 + node * MAXDEG;
        for (int e = 0; e < deg; e++) {
            int s = __ldg(&bucket[e]);
            uint4 u = *(const uint4*)(hx + (long long)s * 128 + sub * 8);
            __half2* hp = (__half2*)&u;
            float2 f0 = __half22float2(hp[0]);
            float2 f1 = __half22float2(hp[1]);
            float2 f2 = __half22float2(hp[2]);
            float2 f3 = __half22float2(hp[3]);
            a0 += f0.x; a1 += f0.y; a2 += f1.x; a3 += f1.y;
            a4 += f2.x; a5 += f2.y; a6 += f3.x; a7 += f3.y;
        }
    } else {
        int E = g_E;
        int e64 = g_e64;
        long long dstBase = e64 ? 2LL * E : (long long)E;
        for (int i = 0; i < E; i++) {
            int dv = e64 ? ei[dstBase + 2LL * i] : ei[dstBase + i];
            if (dv != node) continue;
            int sv = e64 ? ei[2LL * i] : ei[i];
            sv = max(0, min(sv, n - 1));
            uint4 u = *(const uint4*)(hx + (long long)sv * 128 + sub * 8);
            __half2* hp = (__half2*)&u;
            float2 f0 = __half22float2(hp[0]);
            float2 f1 = __half22float2(hp[1]);
            float2 f2 = __half22float2(hp[2]);
            float2 f3 = __half22float2(hp[3]);
            a0 += f0.x; a1 += f0.y; a2 += f1.x; a3 += f1.y;
            a4 += f2.x; a5 += f2.y; a6 += f3.x; a7 += f3.y;
        }
    }
    float inv = 1.0f / fmaxf((float)deg, 1.0f);
    float4 r0 = make_float4(a0 * inv, a1 * inv, a2 * inv, a3 * inv);
    float4 r1 = make_float4(a4 * inv, a5 * inv, a6 * inv, a7 * inv);
    float* op = g_agg + (long long)node * 128 + sub * 8;
    *(float4*)op = r0;
    *(float4*)(op + 4) = r1;
}

// ---------------- split-bf16 HMMA dual GEMM + bias + relu (ldmatrix) --------
// R12 structure (in-kernel fp32 split — empirically fastest load path) with a
// 64x128 CTA tile: warp tile 32x32 (2x4 warp grid), acc 32 regs, 3 CTAs/SM.
#define ASTRIDE 72   // bf16 elems per smem row (64 data + 8 pad): LDSM conflict-free

#define SO_AH 0
#define SO_AL (64 * ASTRIDE)
#define SO_BH (2 * 64 * ASTRIDE)
#define SO_BL (2 * 64 * ASTRIDE + 128 * ASTRIDE)
#define SM_BYTES ((2 * 64 * ASTRIDE + 2 * 128 * ASTRIDE) * 2)

__global__ __launch_bounds__(256, 3)
void hmma_gemm_kernel(const float* __restrict__ A0,   // agg [N,128]
                      const float* __restrict__ A1,   // h   [N,128]
                      const __nv_bfloat16* __restrict__ Bhi,  // [128,256]
                      const __nv_bfloat16* __restrict__ Blo,
                      const float* __restrict__ bias,
                      float* __restrict__ out,
                      __half* __restrict__ outx,      // fp16 copy (or null)
                      int n) {
    extern __shared__ __nv_bfloat16 sm[];
    __nv_bfloat16* sAh = sm + SO_AH;
    __nv_bfloat16* sAl = sm + SO_AL;
    __nv_bfloat16* sBh = sm + SO_BH;
    __nv_bfloat16* sBl = sm + SO_BL;
    uint32_t suAh = smem_u32(sAh);
    uint32_t suAl = smem_u32(sAl);
    uint32_t suBh = smem_u32(sBh);
    uint32_t suBl = smem_u32(sBl);

    int tid = threadIdx.x;
    int wid = tid >> 5;
    int lane = tid & 31;
    int wm = wid & 1;         // m tile (rows wm*32)
    int wn = wid >> 1;        // n quarter (cols wn*32)
    int g = lane >> 2;
    int tg = lane & 3;
    int rowBase = blockIdx.x * 64;
    int mrow = wm * 32;

    // ldmatrix per-lane byte offsets (stride ASTRIDE)
    int laneRowA = (lane & 7) + ((lane >> 3) & 1) * 8;
    int laneKA   = (lane >> 4) * 8;
    uint32_t aOff0 = (uint32_t)(((mrow + laneRowA) * ASTRIDE + laneKA) * 2);
    uint32_t aOff1 = (uint32_t)(((mrow + 16 + laneRowA) * ASTRIDE + laneKA) * 2);
    int laneRowB = (lane & 7) + (lane >> 4) * 8;
    int laneKB   = ((lane >> 3) & 1) * 8;
    uint32_t bOff[2];
#pragma unroll
    for (int p = 0; p < 2; p++)
        bOff[p] = (uint32_t)(((wn * 32 + p * 16 + laneRowB) * ASTRIDE + laneKB) * 2);

    float acc[2][4][4];
#pragma unroll
    for (int mt = 0; mt < 2; mt++)
#pragma unroll
        for (int nt = 0; nt < 4; nt++)
#pragma unroll
            for (int j = 0; j < 4; j++) acc[mt][nt][j] = 0.f;

    for (int kc = 0; kc < 4; kc++) {
        const float* A = (kc < 2) ? A0 : A1;
        int kbase = (kc & 1) * 64;

        // ---- load A chunk: 64 rows x 64 fp32 -> split bf16 hi/lo (4/thread) --
#pragma unroll
        for (int it = 0; it < 4; it++) {
            int idx = tid + it * 256;          // 0..1023 float4s
            int r = idx >> 4;
            int c4 = (idx & 15) * 4;
            int gr = rowBase + r;
            float4 v = make_float4(0.f, 0.f, 0.f, 0.f);
            if (gr < n) v = *(const float4*)(A + (long long)gr * 128 + kbase + c4);
            __nv_bfloat16 hx = __float2bfloat16(v.x), hy = __float2bfloat16(v.y);
            __nv_bfloat16 hz = __float2bfloat16(v.z), hw = __float2bfloat16(v.w);
            __nv_bfloat162 ph0; ph0.x = hx; ph0.y = hy;
            __nv_bfloat162 ph1; ph1.x = hz; ph1.y = hw;
            __nv_bfloat162 pl0, pl1;
            pl0.x = __float2bfloat16(v.x - __bfloat162float(hx));
            pl0.y = __float2bfloat16(v.y - __bfloat162float(hy));
            pl1.x = __float2bfloat16(v.z - __bfloat162float(hz));
            pl1.y = __float2bfloat16(v.w - __bfloat162float(hw));
            int so = r * ASTRIDE + c4;
            *(__nv_bfloat162*)(sAh + so)     = ph0;
            *(__nv_bfloat162*)(sAh + so + 2) = ph1;
            *(__nv_bfloat162*)(sAl + so)     = pl0;
            *(__nv_bfloat162*)(sAl + so + 2) = pl1;
        }
        // ---- load B chunk: 128 rows x 64 bf16 (hi and lo), 4 uint4-pairs/thread
#pragma unroll
        for (int it = 0; it < 4; it++) {
            int idx = tid + it * 256;          // 0..1023 uint4s
            int r = idx >> 3;
            int q = idx & 7;
            uint4 vh = *(const uint4*)(Bhi + r * 256 + kc * 64 + q * 8);
            uint4 vl = *(const uint4*)(Blo + r * 256 + kc * 64 + q * 8);
            *(uint4*)(sBh + r * ASTRIDE + q * 8) = vh;
            *(uint4*)(sBl + r * ASTRIDE + q * 8) = vl;
        }
        __syncthreads();

        // ---- mma over 4 k16 steps, ldmatrix fragment loads ----
#pragma unroll
        for (int ks = 0; ks < 4; ks++) {
            uint32_t kbb = (uint32_t)(ks * 32);     // 16 elems * 2B
            uint32_t ah[2][4], al[2][4];
            ldsm4(ah[0], suAh + aOff0 + kbb);
            ldsm4(ah[1], suAh + aOff1 + kbb);
            ldsm4(al[0], suAl + aOff0 + kbb);
            ldsm4(al[1], suAl + aOff1 + kbb);
#pragma unroll
            for (int p = 0; p < 2; p++) {
                uint32_t bh[4], bl[4];
                ldsm4(bh, suBh + bOff[p] + kbb);
                ldsm4(bl, suBl + bOff[p] + kbb);
#pragma unroll
                for (int mt = 0; mt < 2; mt++) {
                    mma16816(acc[mt][2 * p],     ah[mt], bh);
                    mma16816(acc[mt][2 * p],     ah[mt], bl);
                    mma16816(acc[mt][2 * p],     al[mt], bh);
                    mma16816(acc[mt][2 * p + 1], ah[mt], bh + 2);
                    mma16816(acc[mt][2 * p + 1], ah[mt], bl + 2);
                    mma16816(acc[mt][2 * p + 1], al[mt], bh + 2);
                }
            }
        }
        __syncthreads();
    }

    // ---- epilogue: bias + relu, float2 stores (+ optional fp16 copy) ----
#pragma unroll
    for (int mt = 0; mt < 2; mt++) {
        int gr0 = rowBase + mrow + mt * 16 + g;
        int gr1 = gr0 + 8;
#pragma unroll
        for (int nt = 0; nt < 4; nt++) {
            int col = wn * 32 + nt * 8 + tg * 2;
            float2 bb = *(const float2*)(bias + col);
            if (gr0 < n) {
                float2 o0;
                o0.x = fmaxf(acc[mt][nt][0] + bb.x, 0.f);
                o0.y = fmaxf(acc[mt][nt][1] + bb.y, 0.f);
                *(float2*)(out + (long long)gr0 * 128 + col) = o0;
                if (outx) *(__half2*)(outx + (long long)gr0 * 128 + col) = __floats2half2_rn(o0.x, o0.y);
            }
            if (gr1 < n) {
                float2 o1;
                o1.x = fmaxf(acc[mt][nt][2] + bb.x, 0.f);
                o1.y = fmaxf(acc[mt][nt][3] + bb.y, 0.f);
                *(float2*)(out + (long long)gr1 * 128 + col) = o1;
                if (outx) *(__half2*)(outx + (long long)gr1 * 128 + col) = __floats2half2_rn(o1.x, o1.y);
            }
        }
    }
}

// ---------------- launch ----------------
extern "C" void kernel_launch(void* const* d_in, const int* in_sizes, int n_in,
                              void* d_out, int out_size) {
    // ---- rank-based classification: emb > edge > x > 4x weights > 2x biases ----
    long long sz[32];
    int used[32];
    int m = n_in > 32 ? 32 : n_in;
    for (int i = 0; i < m; i++) { sz[i] = (long long)in_sizes[i]; used[i] = 0; }

    int iEmb = -1, iEdge = -1, iX = -1;
    for (int pass = 0; pass < 3; pass++) {
        long long best = -1; int bi = -1;
        for (int i = 0; i < m; i++)
            if (!used[i] && sz[i] > best) { best = sz[i]; bi = i; }
        used[bi] = 1;
        if (pass == 0) iEmb = bi; else if (pass == 1) iEdge = bi; else iX = bi;
    }
    long long wsz = -1;
    for (int i = 0; i < m; i++) if (!used[i] && sz[i] > wsz) wsz = sz[i];
    const float* Wlist[4] = {0, 0, 0, 0};
    const float* blist[2] = {0, 0};
    int nW = 0, nb = 0;
    for (int i = 0; i < m; i++) {
        if (used[i]) continue;
        if (sz[i] == wsz && nW < 4) Wlist[nW++] = (const float*)d_in[i];
        else if (nb < 2)            blist[nb++] = (const float*)d_in[i];
    }

    const float* emb = (const float*)d_in[iEmb];
    const int*   ei  = (const int*)d_in[iEdge];
    const int*   x   = (const int*)d_in[iX];

    int bytesMode = (sz[iEmb] > 300000000LL) ? 1 : 0;
    long long div = bytesMode ? 4 : 1;
    long long embRows = sz[iEmb] / div / 128;
    long long N_ll = (long long)out_size / (128 * div);
    if (N_ll < 1) N_ll = 1;
    if (N_ll > NN) N_ll = NN;
    int N = (int)N_ll;

    long long eiW = sz[iEdge] / div;
    long long xW  = sz[iX]   / div;
    int elemMode = bytesMode ? 0 : 1;

    long long Emax = eiW / 2; if (Emax > EE) Emax = EE; if (Emax < 1) Emax = 1;

    const float* W1l = Wlist[0];
    const float* W1r = Wlist[1];
    const float* W2l = Wlist[2];
    const float* W2r = Wlist[3];
    const float* b1  = blist[0];
    const float* b2  = blist[1];
    float* out = (float*)d_out;

    // resolve true device addresses of __device__ globals (ATS trap otherwise)
    float *p_h = nullptr, *p_h2 = nullptr, *p_agg = nullptr;
    __half *p_hx = nullptr, *p_h2x = nullptr;
    __nv_bfloat16 *p_bhi1 = nullptr, *p_blo1 = nullptr, *p_bhi2 = nullptr, *p_blo2 = nullptr;
    cudaGetSymbolAddress((void**)&p_h,    g_h);
    cudaGetSymbolAddress((void**)&p_h2,   g_h2);
    cudaGetSymbolAddress((void**)&p_agg,  g_agg);
    cudaGetSymbolAddress((void**)&p_hx,   g_hx);
    cudaGetSymbolAddress((void**)&p_h2x,  g_h2x);
    cudaGetSymbolAddress((void**)&p_bhi1, g_Bhi1);
    cudaGetSymbolAddress((void**)&p_blo1, g_Blo1);
    cudaGetSymbolAddress((void**)&p_bhi2, g_Bhi2);
    cudaGetSymbolAddress((void**)&p_blo2, g_Blo2);

    cudaFuncSetAttribute(hmma_gemm_kernel,
                         cudaFuncAttributeMaxDynamicSharedMemorySize, SM_BYTES);

    int nBlk = (N + 255) / 256;
    int edgeBlocks = (int)((Emax + 255) / 256);
    int gpBlocks = (N * 32 + 2 * 128 * 256 + 255) / 256;

    // ---- pipeline (6 launches) ----
    init_kernel<<<nBlk, 256>>>(ei, eiW, x, xW, elemMode, N);
    build_kernel<<<edgeBlocks + gpBlocks, 256>>>(ei, x, emb, N, embRows,
                                                 W1l, W1r, W2l, W2r, edgeBlocks);

    int aggBlocks = (N * 16 + 255) / 256;
    int gemmBlocks = (N + 63) / 64;

    aggregate_kernel<<<aggBlocks, 256>>>(p_hx, ei, N);
    hmma_gemm_kernel<<<gemmBlocks, 256, SM_BYTES>>>(p_agg, p_h, p_bhi1, p_blo1, b1, p_h2, p_h2x, N);

    aggregate_kernel<<<aggBlocks, 256>>>(p_h2x, ei, N);
    hmma_gemm_kernel<<<gemmBlocks, 256, SM_BYTES>>>(p_agg, p_h2, p_bhi2, p_blo2, b2, out, (__half*)nullptr, N);
}

// round 17
// speedup vs baseline: 1.2781x; 1.2781x over previous
#include <cuda_runtime.h>
#include <cuda_bf16.h>
#include <cuda_fp16.h>
#include <cstdint>

#define NN 50000        // capacity: nodes
#define EE 800000       // capacity: edges
#define HID 128
#define MAXDEG 96       // bucket capacity; P(deg>96) < 1e-30 for this graph

// ---------------- scratch (static __device__, no allocation) ----------------
__device__ float g_h[NN * 128];
__device__ float g_h2[NN * 128];
__device__ float g_agg[NN * 128];
__device__ __half g_hx[NN * 128];    // fp16 copy of h   (aggregation input L1)
__device__ __half g_h2x[NN * 128];   // fp16 copy of h2  (aggregation input L2)
__device__ int   g_cnt[NN];          // per-node edge count
__device__ int   g_csr2[NN * MAXDEG];
__device__ __nv_bfloat16 g_Bhi1[128 * 256];   // B[o][k] = {W1_l | W1_r} hi
__device__ __nv_bfloat16 g_Blo1[128 * 256];   // residual lo
__device__ __nv_bfloat16 g_Bhi2[128 * 256];
__device__ __nv_bfloat16 g_Blo2[128 * 256];
__device__ int   g_E;        // true edge count (device-detected)
__device__ int   g_e64;      // edge_index is int64
__device__ int   g_x64;      // x is int64

// ---------------- warp-level bf16 MMA + ldmatrix (plain PTX) ----------------
__device__ __forceinline__ void mma16816(float* d, const uint32_t* a, const uint32_t* b) {
    asm volatile(
        "mma.sync.aligned.m16n8k16.row.col.f32.bf16.bf16.f32 "
        "{%0,%1,%2,%3}, {%4,%5,%6,%7}, {%8,%9}, {%0,%1,%2,%3};"
        : "+f"(d[0]), "+f"(d[1]), "+f"(d[2]), "+f"(d[3])
        : "r"(a[0]), "r"(a[1]), "r"(a[2]), "r"(a[3]), "r"(b[0]), "r"(b[1]));
}
__device__ __forceinline__ void ldsm4(uint32_t* r, uint32_t addr) {
    asm volatile("ldmatrix.sync.aligned.m8n8.x4.shared.b16 {%0,%1,%2,%3}, [%4];"
        : "=r"(r[0]), "=r"(r[1]), "=r"(r[2]), "=r"(r[3]) : "r"(addr));
}
__device__ __forceinline__ uint32_t smem_u32(const void* p) {
    uint32_t a;
    asm("{ .reg .u64 t; cvta.to.shared.u64 t, %1; cvt.u32.u64 %0, t; }" : "=r"(a) : "l"(p));
    return a;
}

// ---------------- init: zero cnt, thread0 does dtype/count detect ----------
__global__ void init_kernel(const int* __restrict__ ei, long long eiW,
                            const int* __restrict__ x, long long xW,
                            int elemMode, int n) {
    int i = blockIdx.x * blockDim.x + threadIdx.x;
    if (i < n) g_cnt[i] = 0;
    if (blockIdx.x == 0 && threadIdx.x == 0) {
        int e64 = 1;
        for (long long j = 1; j < 256 && j < eiW; j += 2)
            if (ei[j] != 0) { e64 = 0; break; }
        int x64 = 1;
        for (long long j = 1; j < 256 && j < xW; j += 2)
            if (x[j] != 0) { x64 = 0; break; }
        long long E;
        if (elemMode) E = eiW / 2;
        else          E = e64 ? eiW / 4 : eiW / 2;
        if (E > EE) E = EE;
        if (E < 0)  E = 0;
        g_E = (int)E;
        g_e64 = e64;
        g_x64 = x64;
    }
}

// ---------------- fused build: single-pass bucket CSR + gather + weight prep
// Edge phase: 2 edges per thread (issue both atomics back-to-back for MLP).
__global__ void build_kernel(const int* __restrict__ ei,
                             const int* __restrict__ x, const float* __restrict__ emb,
                             int n, long long embRows,
                             const float* __restrict__ W1l, const float* __restrict__ W1r,
                             const float* __restrict__ W2l, const float* __restrict__ W2r,
                             int edgeBlocks) {
    if (blockIdx.x < edgeBlocks) {
        int base = (blockIdx.x * blockDim.x + threadIdx.x) * 2;
        int E = g_E;
        int e64 = g_e64;
        long long dstBase = e64 ? 2LL * E : (long long)E;
#pragma unroll
        for (int u = 0; u < 2; u++) {
            int i = base + u;
            if (i >= E) break;
            int sv = e64 ? ei[2LL * i] : ei[i];
            int dv = e64 ? ei[dstBase + 2LL * i] : ei[dstBase + i];
            sv = max(0, min(sv, n - 1));
            dv = max(0, min(dv, n - 1));
            int pos = atomicAdd(&g_cnt[dv], 1);
            if (pos < MAXDEG) g_csr2[dv * MAXDEG + pos] = sv;
        }
    } else {
        int idx = (blockIdx.x - edgeBlocks) * blockDim.x + threadIdx.x;
        int gWork = n * 32;
        if (idx < gWork) {
            int node = idx >> 5;
            int c4 = (idx & 31) * 4;
            long long row = g_x64 ? (long long)x[2LL * node] : (long long)x[node];
            if (row < 0) row = 0;
            if (row >= embRows) row = embRows - 1;
            float4 v = *(const float4*)(emb + row * 128 + c4);
            *(float4*)(g_h + (long long)node * 128 + c4) = v;
            __half2 p0 = __floats2half2_rn(v.x, v.y);
            __half2 p1 = __floats2half2_rn(v.z, v.w);
            __half2* hp = (__half2*)(g_hx + (long long)node * 128 + c4);
            hp[0] = p0;
            hp[1] = p1;
        } else {
            int w = idx - gWork;
            if (w >= 2 * 128 * 256) return;
            int which = w >> 15;
            int rem = w & 32767;
            int o = rem >> 8;
            int k = rem & 255;
            const float* Wl = which ? W2l : W1l;
            const float* Wr = which ? W2r : W1r;
            float v = (k < 128) ? Wl[o * 128 + k] : Wr[o * 128 + (k - 128)];
            __nv_bfloat16 hi = __float2bfloat16(v);
            __nv_bfloat16 lo = __float2bfloat16(v - __bfloat162float(hi));
            (which ? g_Bhi2 : g_Bhi1)[o * 256 + k] = hi;
            (which ? g_Blo2 : g_Blo1)[o * 256 + k] = lo;
        }
    }
}

// ---------------- mean aggregation: 2 nodes per warp, unroll-2 dual acc -----
__global__ void aggregate_kernel(const __half* __restrict__ hx,
                                 const int* __restrict__ ei, int n) {
    int warp = (blockIdx.x * blockDim.x + threadIdx.x) >> 5;
    int lane = threadIdx.x & 31;
    int node = warp * 2 + (lane >> 4);
    int sub = lane & 15;
    if (node >= n) return;
    int deg = g_cnt[node];
    // two independent accumulator sets break the FADD dependency chain
    float a0 = 0.f, a1 = 0.f, a2 = 0.f, a3 = 0.f;
    float a4 = 0.f, a5 = 0.f, a6 = 0.f, a7 = 0.f;
    float b0 = 0.f, b1 = 0.f, b2 = 0.f, b3 = 0.f;
    float b4 = 0.f, b5 = 0.f, b6 = 0.f, b7 = 0.f;
    if (deg <= MAXDEG) {
        const int* bucket = g_csr2 + node * MAXDEG;
        int e = 0;
        for (; e + 2 <= deg; e += 2) {
            int s0 = __ldg(&bucket[e]);
            int s1 = __ldg(&bucket[e + 1]);
            uint4 u0 = *(const uint4*)(hx + (long long)s0 * 128 + sub * 8);
            uint4 u1 = *(const uint4*)(hx + (long long)s1 * 128 + sub * 8);
            __half2* h0 = (__half2*)&u0;
            __half2* h1 = (__half2*)&u1;
            float2 f;
            f = __half22float2(h0[0]); a0 += f.x; a1 += f.y;
            f = __half22float2(h0[1]); a2 += f.x; a3 += f.y;
            f = __half22float2(h0[2]); a4 += f.x; a5 += f.y;
            f = __half22float2(h0[3]); a6 += f.x; a7 += f.y;
            f = __half22float2(h1[0]); b0 += f.x; b1 += f.y;
            f = __half22float2(h1[1]); b2 += f.x; b3 += f.y;
            f = __half22float2(h1[2]); b4 += f.x; b5 += f.y;
            f = __half22float2(h1[3]); b6 += f.x; b7 += f.y;
        }
        if (e < deg) {
            int s0 = __ldg(&bucket[e]);
            uint4 u0 = *(const uint4*)(hx + (long long)s0 * 128 + sub * 8);
            __half2* h0 = (__half2*)&u0;
            float2 f;
            f = __half22float2(h0[0]); a0 += f.x; a1 += f.y;
            f = __half22float2(h0[1]); a2 += f.x; a3 += f.y;
            f = __half22float2(h0[2]); a4 += f.x; a5 += f.y;
            f = __half22float2(h0[3]); a6 += f.x; a7 += f.y;
        }
    } else {
        // exact fallback: scan every edge (statistically unreachable)
        int E = g_E;
        int e64 = g_e64;
        long long dstBase = e64 ? 2LL * E : (long long)E;
        for (int i = 0; i < E; i++) {
            int dv = e64 ? ei[dstBase + 2LL * i] : ei[dstBase + i];
            if (dv != node) continue;
            int sv = e64 ? ei[2LL * i] : ei[i];
            sv = max(0, min(sv, n - 1));
            uint4 u0 = *(const uint4*)(hx + (long long)sv * 128 + sub * 8);
            __half2* h0 = (__half2*)&u0;
            float2 f;
            f = __half22float2(h0[0]); a0 += f.x; a1 += f.y;
            f = __half22float2(h0[1]); a2 += f.x; a3 += f.y;
            f = __half22float2(h0[2]); a4 += f.x; a5 += f.y;
            f = __half22float2(h0[3]); a6 += f.x; a7 += f.y;
        }
    }
    float inv = 1.0f / fmaxf((float)deg, 1.0f);
    float4 r0 = make_float4((a0 + b0) * inv, (a1 + b1) * inv,
                            (a2 + b2) * inv, (a3 + b3) * inv);
    float4 r1 = make_float4((a4 + b4) * inv, (a5 + b5) * inv,
                            (a6 + b6) * inv, (a7 + b7) * inv);
    float* op = g_agg + (long long)node * 128 + sub * 8;
    *(float4*)op = r0;
    *(float4*)(op + 4) = r1;
}

// ---------------- split-bf16 HMMA dual GEMM + bias + relu (R12, unchanged) --
#define ASTRIDE 72   // bf16 elems per smem row (64 data + 8 pad): LDSM conflict-free

#define SO_AH 0
#define SO_AL (128 * ASTRIDE)
#define SO_BH (2 * 128 * ASTRIDE)
#define SO_BL (3 * 128 * ASTRIDE)
#define SM_BYTES (4 * 128 * ASTRIDE * 2)

__global__ __launch_bounds__(256, 2)
void hmma_gemm_kernel(const float* __restrict__ A0,   // agg [N,128]
                      const float* __restrict__ A1,   // h   [N,128]
                      const __nv_bfloat16* __restrict__ Bhi,  // [128,256]
                      const __nv_bfloat16* __restrict__ Blo,
                      const float* __restrict__ bias,
                      float* __restrict__ out,
                      __half* __restrict__ outx,      // fp16 copy (or null)
                      int n) {
    extern __shared__ __nv_bfloat16 sm[];
    __nv_bfloat16* sAh = sm + SO_AH;
    __nv_bfloat16* sAl = sm + SO_AL;
    __nv_bfloat16* sBh = sm + SO_BH;
    __nv_bfloat16* sBl = sm + SO_BL;
    uint32_t suAh = smem_u32(sAh);
    uint32_t suAl = smem_u32(sAl);
    uint32_t suBh = smem_u32(sBh);
    uint32_t suBl = smem_u32(sBl);

    int tid = threadIdx.x;
    int wid = tid >> 5;
    int lane = tid & 31;
    int wm = wid & 3;         // m tile (rows wm*32)
    int wn = wid >> 2;        // n half (cols wn*64)
    int g = lane >> 2;
    int tg = lane & 3;
    int rowBase = blockIdx.x * 128;
    int mrow = wm * 32;

    // ldmatrix per-lane byte offsets (stride ASTRIDE)
    int laneRowA = (lane & 7) + ((lane >> 3) & 1) * 8;
    int laneKA   = (lane >> 4) * 8;
    uint32_t aOff0 = (uint32_t)(((mrow + laneRowA) * ASTRIDE + laneKA) * 2);
    uint32_t aOff1 = (uint32_t)(((mrow + 16 + laneRowA) * ASTRIDE + laneKA) * 2);
    int laneRowB = (lane & 7) + (lane >> 4) * 8;
    int laneKB   = ((lane >> 3) & 1) * 8;
    uint32_t bOff[4];
#pragma unroll
    for (int p = 0; p < 4; p++)
        bOff[p] = (uint32_t)(((wn * 64 + p * 16 + laneRowB) * ASTRIDE + laneKB) * 2);

    float acc[2][8][4];
#pragma unroll
    for (int mt = 0; mt < 2; mt++)
#pragma unroll
        for (int nt = 0; nt < 8; nt++)
#pragma unroll
            for (int j = 0; j < 4; j++) acc[mt][nt][j] = 0.f;

    for (int kc = 0; kc < 4; kc++) {
        const float* A = (kc < 2) ? A0 : A1;
        int kbase = (kc & 1) * 64;

        // ---- load A chunk: 128 rows x 64 fp32 -> split bf16 hi/lo ----
#pragma unroll
        for (int it = 0; it < 8; it++) {
            int idx = tid + it * 256;          // 0..2047 float4s
            int r = idx >> 4;
            int c4 = (idx & 15) * 4;
            int gr = rowBase + r;
            float4 v = make_float4(0.f, 0.f, 0.f, 0.f);
            if (gr < n) v = *(const float4*)(A + (long long)gr * 128 + kbase + c4);
            __nv_bfloat16 hx = __float2bfloat16(v.x), hy = __float2bfloat16(v.y);
            __nv_bfloat16 hz = __float2bfloat16(v.z), hw = __float2bfloat16(v.w);
            __nv_bfloat162 ph0; ph0.x = hx; ph0.y = hy;
            __nv_bfloat162 ph1; ph1.x = hz; ph1.y = hw;
            __nv_bfloat162 pl0, pl1;
            pl0.x = __float2bfloat16(v.x - __bfloat162float(hx));
            pl0.y = __float2bfloat16(v.y - __bfloat162float(hy));
            pl1.x = __float2bfloat16(v.z - __bfloat162float(hz));
            pl1.y = __float2bfloat16(v.w - __bfloat162float(hw));
            int so = r * ASTRIDE + c4;
            *(__nv_bfloat162*)(sAh + so)     = ph0;
            *(__nv_bfloat162*)(sAh + so + 2) = ph1;
            *(__nv_bfloat162*)(sAl + so)     = pl0;
            *(__nv_bfloat162*)(sAl + so + 2) = pl1;
        }
        // ---- load B chunk: 128 rows x 64 bf16 (hi and lo) ----
#pragma unroll
        for (int it = 0; it < 4; it++) {
            int idx = tid + it * 256;          // 0..1023 uint4s
            int r = idx >> 3;
            int q = idx & 7;
            uint4 vh = *(const uint4*)(Bhi + r * 256 + kc * 64 + q * 8);
            uint4 vl = *(const uint4*)(Blo + r * 256 + kc * 64 + q * 8);
            *(uint4*)(sBh + r * ASTRIDE + q * 8) = vh;
            *(uint4*)(sBl + r * ASTRIDE + q * 8) = vl;
        }
        __syncthreads();

        // ---- mma over 4 k16 steps, ldmatrix fragment loads ----
#pragma unroll
        for (int ks = 0; ks < 4; ks++) {
            uint32_t kbb = (uint32_t)(ks * 32);     // 16 elems * 2B
            uint32_t ah[2][4], al[2][4];
            ldsm4(ah[0], suAh + aOff0 + kbb);
            ldsm4(ah[1], suAh + aOff1 + kbb);
            ldsm4(al[0], suAl + aOff0 + kbb);
            ldsm4(al[1], suAl + aOff1 + kbb);
#pragma unroll
            for (int p = 0; p < 4; p++) {
                uint32_t bh[4], bl[4];
                ldsm4(bh, suBh + bOff[p] + kbb);
                ldsm4(bl, suBl + bOff[p] + kbb);
#pragma unroll
                for (int mt = 0; mt < 2; mt++) {
                    mma16816(acc[mt][2 * p],     ah[mt], bh);
                    mma16816(acc[mt][2 * p],     ah[mt], bl);
                    mma16816(acc[mt][2 * p],     al[mt], bh);
                    mma16816(acc[mt][2 * p + 1], ah[mt], bh + 2);
                    mma16816(acc[mt][2 * p + 1], ah[mt], bl + 2);
                    mma16816(acc[mt][2 * p + 1], al[mt], bh + 2);
                }
            }
        }
        __syncthreads();
    }

    // ---- epilogue: bias + relu, float2 stores (+ optional fp16 copy) ----
#pragma unroll
    for (int mt = 0; mt < 2; mt++) {
        int gr0 = rowBase + mrow + mt * 16 + g;
        int gr1 = gr0 + 8;
#pragma unroll
        for (int nt = 0; nt < 8; nt++) {
            int col = wn * 64 + nt * 8 + tg * 2;
            float2 bb = *(const float2*)(bias + col);
            if (gr0 < n) {
                float2 o0;
                o0.x = fmaxf(acc[mt][nt][0] + bb.x, 0.f);
                o0.y = fmaxf(acc[mt][nt][1] + bb.y, 0.f);
                *(float2*)(out + (long long)gr0 * 128 + col) = o0;
                if (outx) *(__half2*)(outx + (long long)gr0 * 128 + col) = __floats2half2_rn(o0.x, o0.y);
            }
            if (gr1 < n) {
                float2 o1;
                o1.x = fmaxf(acc[mt][nt][2] + bb.x, 0.f);
                o1.y = fmaxf(acc[mt][nt][3] + bb.y, 0.f);
                *(float2*)(out + (long long)gr1 * 128 + col) = o1;
                if (outx) *(__half2*)(outx + (long long)gr1 * 128 + col) = __floats2half2_rn(o1.x, o1.y);
            }
        }
    }
}

// ---------------- launch ----------------
extern "C" void kernel_launch(void* const* d_in, const int* in_sizes, int n_in,
                              void* d_out, int out_size) {
    // ---- rank-based classification: emb > edge > x > 4x weights > 2x biases ----
    long long sz[32];
    int used[32];
    int m = n_in > 32 ? 32 : n_in;
    for (int i = 0; i < m; i++) { sz[i] = (long long)in_sizes[i]; used[i] = 0; }

    int iEmb = -1, iEdge = -1, iX = -1;
    for (int pass = 0; pass < 3; pass++) {
        long long best = -1; int bi = -1;
        for (int i = 0; i < m; i++)
            if (!used[i] && sz[i] > best) { best = sz[i]; bi = i; }
        used[bi] = 1;
        if (pass == 0) iEmb = bi; else if (pass == 1) iEdge = bi; else iX = bi;
    }
    long long wsz = -1;
    for (int i = 0; i < m; i++) if (!used[i] && sz[i] > wsz) wsz = sz[i];
    const float* Wlist[4] = {0, 0, 0, 0};
    const float* blist[2] = {0, 0};
    int nW = 0, nb = 0;
    for (int i = 0; i < m; i++) {
        if (used[i]) continue;
        if (sz[i] == wsz && nW < 4) Wlist[nW++] = (const float*)d_in[i];
        else if (nb < 2)            blist[nb++] = (const float*)d_in[i];
    }

    const float* emb = (const float*)d_in[iEmb];
    const int*   ei  = (const int*)d_in[iEdge];
    const int*   x   = (const int*)d_in[iX];

    int bytesMode = (sz[iEmb] > 300000000LL) ? 1 : 0;
    long long div = bytesMode ? 4 : 1;
    long long embRows = sz[iEmb] / div / 128;
    long long N_ll = (long long)out_size / (128 * div);
    if (N_ll < 1) N_ll = 1;
    if (N_ll > NN) N_ll = NN;
    int N = (int)N_ll;

    long long eiW = sz[iEdge] / div;
    long long xW  = sz[iX]   / div;
    int elemMode = bytesMode ? 0 : 1;

    long long Emax = eiW / 2; if (Emax > EE) Emax = EE; if (Emax < 1) Emax = 1;

    const float* W1l = Wlist[0];
    const float* W1r = Wlist[1];
    const float* W2l = Wlist[2];
    const float* W2r = Wlist[3];
    const float* b1  = blist[0];
    const float* b2  = blist[1];
    float* out = (float*)d_out;

    // resolve true device addresses of __device__ globals (ATS trap otherwise)
    float *p_h = nullptr, *p_h2 = nullptr, *p_agg = nullptr;
    __half *p_hx = nullptr, *p_h2x = nullptr;
    __nv_bfloat16 *p_bhi1 = nullptr, *p_blo1 = nullptr, *p_bhi2 = nullptr, *p_blo2 = nullptr;
    cudaGetSymbolAddress((void**)&p_h,    g_h);
    cudaGetSymbolAddress((void**)&p_h2,   g_h2);
    cudaGetSymbolAddress((void**)&p_agg,  g_agg);
    cudaGetSymbolAddress((void**)&p_hx,   g_hx);
    cudaGetSymbolAddress((void**)&p_h2x,  g_h2x);
    cudaGetSymbolAddress((void**)&p_bhi1, g_Bhi1);
    cudaGetSymbolAddress((void**)&p_blo1, g_Blo1);
    cudaGetSymbolAddress((void**)&p_bhi2, g_Bhi2);
    cudaGetSymbolAddress((void**)&p_blo2, g_Blo2);

    cudaFuncSetAttribute(hmma_gemm_kernel,
                         cudaFuncAttributeMaxDynamicSharedMemorySize, SM_BYTES);

    int nBlk = (N + 255) / 256;
    int edgeBlocks = (int)((Emax + 511) / 512);   // 2 edges per thread
    int gpBlocks = (N * 32 + 2 * 128 * 256 + 255) / 256;

    // ---- pipeline (6 launches) ----
    init_kernel<<<nBlk, 256>>>(ei, eiW, x, xW, elemMode, N);
    build_kernel<<<edgeBlocks + gpBlocks, 256>>>(ei, x, emb, N, embRows,
                                                 W1l, W1r, W2l, W2r, edgeBlocks);

    int aggBlocks = (N * 16 + 255) / 256;
    int gemmBlocks = (N + 127) / 128;

    aggregate_kernel<<<aggBlocks, 256>>>(p_hx, ei, N);
    hmma_gemm_kernel<<<gemmBlocks, 256, SM_BYTES>>>(p_agg, p_h, p_bhi1, p_blo1, b1, p_h2, p_h2x, N);

    aggregate_kernel<<<aggBlocks, 256>>>(p_h2x, ei, N);
    hmma_gemm_kernel<<<gemmBlocks, 256, SM_BYTES>>>(p_agg, p_h2, p_bhi2, p_blo2, b2, out, (__half*)nullptr, N);
}